// round 3
// baseline (speedup 1.0000x reference)
#include <cuda_runtime.h>

// Sorted segment-sum: pred_rgb[r] = sum_{i in ray r} w[i] * rgb[i]
// N_SAMPLES = 4194304, N_RAYS = 65536, indices sorted ascending.
//
// R2: occupancy-oriented restructure. R1 front-batched 80 floats into
// registers (regs=90 -> 2 CTAs/SM -> occ 22.7%, DRAM 54%). Now each
// 4-sample group is loaded and consumed immediately (live set ~25 regs),
// and __launch_bounds__(256, 6) caps regs at ~42 -> 6 CTAs/SM = 48 warps.
// Latency-hiding comes from warp parallelism instead of per-thread MLP.

#define ITEMS 16
#define TPB 256

__global__ void zero_out_kernel(float4* __restrict__ out, int n4) {
    int i = blockIdx.x * blockDim.x + threadIdx.x;
    if (i < n4) out[i] = make_float4(0.f, 0.f, 0.f, 0.f);
}

__global__ __launch_bounds__(TPB, 6) void seg_sum_kernel(
    const float* __restrict__ rgb,
    const float* __restrict__ w,
    const int*   __restrict__ idx,
    float* __restrict__ out,
    int n)
{
    long long base = (long long)(blockIdx.x * TPB + threadIdx.x) * ITEMS;
    if (base >= n) return;

    const int4*   idx4 = reinterpret_cast<const int4*>(idx + base);
    const float4* w4   = reinterpret_cast<const float4*>(w + base);
    const float4* r4   = reinterpret_cast<const float4*>(rgb + base * 3);

    int cur = -1;               // sentinel; first sample always "changes"
    float a0 = 0.f, a1 = 0.f, a2 = 0.f;
    bool first = true;

    #pragma unroll
    for (int g = 0; g < ITEMS / 4; g++) {
        // Load one group: 5 independent LDG.128
        int4   i4 = idx4[g];
        float4 wv = w4[g];
        float4 ra = r4[g * 3 + 0];
        float4 rb = r4[g * 3 + 1];
        float4 rc = r4[g * 3 + 2];

        int   id[4] = {i4.x, i4.y, i4.z, i4.w};
        float wt[4] = {wv.x, wv.y, wv.z, wv.w};
        float rv[12] = {ra.x, ra.y, ra.z, ra.w,
                        rb.x, rb.y, rb.z, rb.w,
                        rc.x, rc.y, rc.z, rc.w};

        if (g == 0) { cur = id[0]; first = false; }

        #pragma unroll
        for (int i = 0; i < 4; i++) {
            if (id[i] != cur) {
                atomicAdd(&out[cur * 3 + 0], a0);
                atomicAdd(&out[cur * 3 + 1], a1);
                atomicAdd(&out[cur * 3 + 2], a2);
                cur = id[i];
                a0 = a1 = a2 = 0.f;
            }
            float wi = wt[i];
            a0 = fmaf(wi, rv[i * 3 + 0], a0);
            a1 = fmaf(wi, rv[i * 3 + 1], a1);
            a2 = fmaf(wi, rv[i * 3 + 2], a2);
        }
    }
    (void)first;
    atomicAdd(&out[cur * 3 + 0], a0);
    atomicAdd(&out[cur * 3 + 1], a1);
    atomicAdd(&out[cur * 3 + 2], a2);
}

extern "C" void kernel_launch(void* const* d_in, const int* in_sizes, int n_in,
                              void* d_out, int out_size)
{
    const float* rgb = (const float*)d_in[0];
    const float* w   = (const float*)d_in[1];
    const int*   idx = (const int*)d_in[2];
    float* out = (float*)d_out;

    int n = in_sizes[2];  // number of samples

    // out_size = 65536*3 = 196608 floats, divisible by 4.
    int n4 = out_size / 4;
    int zb = (n4 + TPB - 1) / TPB;
    zero_out_kernel<<<zb, TPB>>>((float4*)out, n4);

    int total_threads = (n + ITEMS - 1) / ITEMS;
    int blocks = (total_threads + TPB - 1) / TPB;
    seg_sum_kernel<<<blocks, TPB>>>(rgb, w, idx, out, n);
}

// round 4
// speedup vs baseline: 1.0828x; 1.0828x over previous
#include <cuda_runtime.h>

// Sorted segment-sum: pred_rgb[r] = sum_{i in ray r} w[i] * rgb[i]
// N_SAMPLES = 4194304, N_RAYS = 65536, indices sorted ascending.
//
// R3: persistent kernel + explicit register double-buffer.
// R1/R2 post-mortem: one-shot CTAs alternate load-burst / compute phases,
// leaving the memory pipe idle half the time (DRAM stuck at 45-54%).
// Now 296 persistent CTAs grid-stride over 8-sample tiles; each thread
// loads tile t+stride into buffer B while consuming buffer A, so 10
// independent LDG.128 per warp-slot are always in flight.

#define TPB   256
#define ITEMS 8
#define NBLK  296   // 2 CTAs/SM x 148 SMs

struct Tile {
    int4   i0, i1;                 // 8 ray indices
    float4 w0, w1;                 // 8 weights
    float4 r0, r1, r2, r3, r4, r5; // 24 rgb floats
};

__device__ __forceinline__ void load_tile(
    Tile& tb, const int* __restrict__ idx, const float* __restrict__ w,
    const float* __restrict__ rgb, long long t)
{
    long long base = t * ITEMS;
    const int4*   ip = reinterpret_cast<const int4*>(idx + base);
    const float4* wp = reinterpret_cast<const float4*>(w + base);
    const float4* rp = reinterpret_cast<const float4*>(rgb + base * 3);
    tb.i0 = ip[0]; tb.i1 = ip[1];
    tb.w0 = wp[0]; tb.w1 = wp[1];
    tb.r0 = rp[0]; tb.r1 = rp[1]; tb.r2 = rp[2];
    tb.r3 = rp[3]; tb.r4 = rp[4]; tb.r5 = rp[5];
}

__device__ __forceinline__ void consume_tile(const Tile& tb, float* __restrict__ out)
{
    int   id[8] = {tb.i0.x, tb.i0.y, tb.i0.z, tb.i0.w,
                   tb.i1.x, tb.i1.y, tb.i1.z, tb.i1.w};
    float wt[8] = {tb.w0.x, tb.w0.y, tb.w0.z, tb.w0.w,
                   tb.w1.x, tb.w1.y, tb.w1.z, tb.w1.w};
    float rv[24] = {tb.r0.x, tb.r0.y, tb.r0.z, tb.r0.w,
                    tb.r1.x, tb.r1.y, tb.r1.z, tb.r1.w,
                    tb.r2.x, tb.r2.y, tb.r2.z, tb.r2.w,
                    tb.r3.x, tb.r3.y, tb.r3.z, tb.r3.w,
                    tb.r4.x, tb.r4.y, tb.r4.z, tb.r4.w,
                    tb.r5.x, tb.r5.y, tb.r5.z, tb.r5.w};

    int cur = id[0];
    float a0 = 0.f, a1 = 0.f, a2 = 0.f;
    #pragma unroll
    for (int i = 0; i < 8; i++) {
        if (id[i] != cur) {
            atomicAdd(&out[cur * 3 + 0], a0);
            atomicAdd(&out[cur * 3 + 1], a1);
            atomicAdd(&out[cur * 3 + 2], a2);
            cur = id[i];
            a0 = a1 = a2 = 0.f;
        }
        float wi = wt[i];
        a0 = fmaf(wi, rv[i * 3 + 0], a0);
        a1 = fmaf(wi, rv[i * 3 + 1], a1);
        a2 = fmaf(wi, rv[i * 3 + 2], a2);
    }
    atomicAdd(&out[cur * 3 + 0], a0);
    atomicAdd(&out[cur * 3 + 1], a1);
    atomicAdd(&out[cur * 3 + 2], a2);
}

__global__ void zero_out_kernel(float4* __restrict__ out, int n4) {
    int i = blockIdx.x * blockDim.x + threadIdx.x;
    if (i < n4) out[i] = make_float4(0.f, 0.f, 0.f, 0.f);
}

__global__ __launch_bounds__(TPB, 2) void seg_sum_kernel(
    const float* __restrict__ rgb,
    const float* __restrict__ w,
    const int*   __restrict__ idx,
    float* __restrict__ out,
    int n)
{
    const long long total_tiles = n / ITEMS;
    const long long stride = (long long)gridDim.x * TPB;
    long long t = (long long)blockIdx.x * TPB + threadIdx.x;

    // Scalar tail for n % ITEMS (normally 0 for this problem size).
    if (blockIdx.x == 0 && threadIdx.x == 0) {
        for (long long s = total_tiles * ITEMS; s < n; s++) {
            float wi = w[s];
            int r = idx[s];
            atomicAdd(&out[r * 3 + 0], wi * rgb[s * 3 + 0]);
            atomicAdd(&out[r * 3 + 1], wi * rgb[s * 3 + 1]);
            atomicAdd(&out[r * 3 + 2], wi * rgb[s * 3 + 2]);
        }
    }

    if (t >= total_tiles) return;

    Tile bufA, bufB;
    load_tile(bufA, idx, w, rgb, t);

    while (true) {
        long long t1 = t + stride;
        bool v1 = t1 < total_tiles;
        if (v1) load_tile(bufB, idx, w, rgb, t1);   // prefetch next
        consume_tile(bufA, out);                     // consume current
        if (!v1) return;

        long long t2 = t1 + stride;
        bool v2 = t2 < total_tiles;
        if (v2) load_tile(bufA, idx, w, rgb, t2);   // prefetch next
        consume_tile(bufB, out);
        if (!v2) return;
        t = t2;
    }
}

extern "C" void kernel_launch(void* const* d_in, const int* in_sizes, int n_in,
                              void* d_out, int out_size)
{
    const float* rgb = (const float*)d_in[0];
    const float* w   = (const float*)d_in[1];
    const int*   idx = (const int*)d_in[2];
    float* out = (float*)d_out;

    int n = in_sizes[2];  // number of samples

    int n4 = out_size / 4;  // 196608 / 4
    int zb = (n4 + TPB - 1) / TPB;
    zero_out_kernel<<<zb, TPB>>>((float4*)out, n4);

    long long total_tiles = n / ITEMS;
    int blocks = NBLK;
    long long max_needed = (total_tiles + TPB - 1) / TPB;
    if (max_needed < blocks) blocks = (int)max_needed;
    if (blocks < 1) blocks = 1;
    seg_sum_kernel<<<blocks, TPB>>>(rgb, w, idx, out, n);
}

// round 5
// speedup vs baseline: 1.2166x; 1.1235x over previous
#include <cuda_runtime.h>
#include <cstdint>

// Sorted segment-sum: pred_rgb[r] = sum_{i in ray r} w[i] * rgb[i]
// N_SAMPLES = 4194304, N_RAYS = 65536, indices sorted ascending.
//
// R4: TMA (cp.async.bulk) -> smem ring pipeline, persistent 1 CTA/SM.
// R1-R3 post-mortem: LDG-based kernels pin at 45-54% DRAM regardless of
// occupancy/MLP -- the per-SM LDG in-flight path saturates. TMA bulk
// copies keep a 4-deep 40KB-stage ring (~120KB/SM) in flight via the
// copy engine; consumers run the proven register run-accumulate +
// boundary-atomic scheme out of shared memory.

#define TPB          256
#define STAGE_SAMPLES 2048
#define SPT          8                  // contiguous samples per thread
#define NSTAGE       4                  // ring depth
#define IDX_B        (STAGE_SAMPLES * 4)         // 8192
#define W_B          (STAGE_SAMPLES * 4)         // 8192
#define RGB_B        (STAGE_SAMPLES * 12)        // 24576
#define STAGE_B      (IDX_B + W_B + RGB_B)       // 40960
#define DATA_OFF     128                          // barriers live below
#define SMEM_TOTAL   (DATA_OFF + NSTAGE * STAGE_B)

__device__ __forceinline__ uint32_t smem_u32(const void* p) {
    uint32_t a;
    asm("{ .reg .u64 t; cvta.to.shared.u64 t, %1; cvt.u32.u64 %0, t; }"
        : "=r"(a) : "l"(p));
    return a;
}

__device__ __forceinline__ void mbar_init(uint32_t mbar, uint32_t count) {
    asm volatile("mbarrier.init.shared.b64 [%0], %1;" :: "r"(mbar), "r"(count) : "memory");
}
__device__ __forceinline__ void mbar_expect_tx(uint32_t mbar, uint32_t bytes) {
    asm volatile("mbarrier.arrive.expect_tx.shared.b64 _, [%0], %1;"
                 :: "r"(mbar), "r"(bytes) : "memory");
}
__device__ __forceinline__ void mbar_wait(uint32_t mbar, uint32_t parity) {
    uint32_t done;
    asm volatile(
        "{\n\t.reg .pred p;\n\t"
        "mbarrier.try_wait.parity.acquire.cta.shared::cta.b64 p, [%1], %2;\n\t"
        "selp.b32 %0, 1, 0, p;\n\t}"
        : "=r"(done) : "r"(mbar), "r"(parity) : "memory");
    if (!done) {
        asm volatile(
            "{\n\t.reg .pred P1;\n\t"
            "W_%=:\n\t"
            "mbarrier.try_wait.parity.acquire.cta.shared::cta.b64 P1, [%0], %1, 0x989680;\n\t"
            "@P1 bra.uni D_%=;\n\t"
            "bra.uni W_%=;\n\t"
            "D_%=:\n\t}"
            :: "r"(mbar), "r"(parity) : "memory");
    }
}
__device__ __forceinline__ void bulk_g2s(uint32_t dst, const void* src,
                                         uint32_t bytes, uint32_t mbar) {
    asm volatile(
        "cp.async.bulk.shared::cta.global.mbarrier::complete_tx::bytes [%0], [%1], %2, [%3];"
        :: "r"(dst), "l"(src), "r"(bytes), "r"(mbar) : "memory");
}

__global__ void zero_out_kernel(float* __restrict__ out, int n) {
    int i = (blockIdx.x * blockDim.x + threadIdx.x) * 4;
    if (i + 3 < n) {
        *reinterpret_cast<float4*>(out + i) = make_float4(0.f, 0.f, 0.f, 0.f);
    } else {
        for (int j = i; j < n; j++) out[j] = 0.f;
    }
}

__global__ __launch_bounds__(TPB, 1) void seg_sum_kernel(
    const float* __restrict__ rgb,
    const float* __restrict__ w,
    const int*   __restrict__ idx,
    float* __restrict__ out,
    int n)
{
    extern __shared__ __align__(128) char smem[];
    const int tid = threadIdx.x;
    const uint32_t smem_base = smem_u32(smem);

    const int total_stages = n / STAGE_SAMPLES;
    const int G = gridDim.x;

    // Scalar tail for n % STAGE_SAMPLES (0 for this problem size).
    if (blockIdx.x == 0 && tid == 0) {
        for (long long s = (long long)total_stages * STAGE_SAMPLES; s < n; s++) {
            float wi = w[s];
            int r = idx[s];
            atomicAdd(&out[r * 3 + 0], wi * rgb[s * 3 + 0]);
            atomicAdd(&out[r * 3 + 1], wi * rgb[s * 3 + 1]);
            atomicAdd(&out[r * 3 + 2], wi * rgb[s * 3 + 2]);
        }
    }

    // Stages owned by this CTA: bid, bid+G, bid+2G, ...
    int nmine = 0;
    for (int g = blockIdx.x; g < total_stages; g += G) nmine++;
    if (nmine == 0) return;

    if (tid == 0) {
        #pragma unroll
        for (int s = 0; s < NSTAGE; s++) mbar_init(smem_base + s * 8, 1);
    }
    __syncthreads();

    // Prologue: fill the ring.
    if (tid == 0) {
        int npro = nmine < NSTAGE ? nmine : NSTAGE;
        for (int k = 0; k < npro; k++) {
            int g = blockIdx.x + k * G;
            long long base = (long long)g * STAGE_SAMPLES;
            uint32_t mb  = smem_base + k * 8;
            uint32_t dst = smem_base + DATA_OFF + k * STAGE_B;
            mbar_expect_tx(mb, STAGE_B);
            bulk_g2s(dst,              idx + base,     IDX_B, mb);
            bulk_g2s(dst + IDX_B,      w   + base,     W_B,   mb);
            bulk_g2s(dst + IDX_B + W_B, rgb + base * 3, RGB_B, mb);
        }
    }

    for (int k = 0; k < nmine; k++) {
        const int slot = k & (NSTAGE - 1);
        const uint32_t parity = (k / NSTAGE) & 1;
        mbar_wait(smem_base + slot * 8, parity);

        // Consume: thread t owns 8 contiguous samples of this stage.
        {
            const char* sd = smem + DATA_OFF + slot * STAGE_B;
            const int4*   ip = reinterpret_cast<const int4*>(sd + tid * 32);
            const float4* wp = reinterpret_cast<const float4*>(sd + IDX_B + tid * 32);
            const float4* rp = reinterpret_cast<const float4*>(sd + IDX_B + W_B + tid * 96);

            int4   i0 = ip[0], i1 = ip[1];
            float4 w0 = wp[0], w1 = wp[1];
            float4 r0 = rp[0], r1 = rp[1], r2 = rp[2];
            float4 r3 = rp[3], r4 = rp[4], r5 = rp[5];

            int   id[8] = {i0.x, i0.y, i0.z, i0.w, i1.x, i1.y, i1.z, i1.w};
            float wt[8] = {w0.x, w0.y, w0.z, w0.w, w1.x, w1.y, w1.z, w1.w};
            float rv[24] = {r0.x, r0.y, r0.z, r0.w, r1.x, r1.y, r1.z, r1.w,
                            r2.x, r2.y, r2.z, r2.w, r3.x, r3.y, r3.z, r3.w,
                            r4.x, r4.y, r4.z, r4.w, r5.x, r5.y, r5.z, r5.w};

            int cur = id[0];
            float a0 = 0.f, a1 = 0.f, a2 = 0.f;
            #pragma unroll
            for (int i = 0; i < 8; i++) {
                if (id[i] != cur) {
                    atomicAdd(&out[cur * 3 + 0], a0);
                    atomicAdd(&out[cur * 3 + 1], a1);
                    atomicAdd(&out[cur * 3 + 2], a2);
                    cur = id[i];
                    a0 = a1 = a2 = 0.f;
                }
                float wi = wt[i];
                a0 = fmaf(wi, rv[i * 3 + 0], a0);
                a1 = fmaf(wi, rv[i * 3 + 1], a1);
                a2 = fmaf(wi, rv[i * 3 + 2], a2);
            }
            atomicAdd(&out[cur * 3 + 0], a0);
            atomicAdd(&out[cur * 3 + 1], a1);
            atomicAdd(&out[cur * 3 + 2], a2);
        }

        __syncthreads();   // slot fully consumed -> safe to refill

        if (tid == 0 && k + NSTAGE < nmine) {
            int g = blockIdx.x + (k + NSTAGE) * G;
            long long base = (long long)g * STAGE_SAMPLES;
            uint32_t mb  = smem_base + slot * 8;
            uint32_t dst = smem_base + DATA_OFF + slot * STAGE_B;
            mbar_expect_tx(mb, STAGE_B);
            bulk_g2s(dst,               idx + base,     IDX_B, mb);
            bulk_g2s(dst + IDX_B,       w   + base,     W_B,   mb);
            bulk_g2s(dst + IDX_B + W_B, rgb + base * 3, RGB_B, mb);
        }
    }
}

extern "C" void kernel_launch(void* const* d_in, const int* in_sizes, int n_in,
                              void* d_out, int out_size)
{
    const float* rgb = (const float*)d_in[0];
    const float* w   = (const float*)d_in[1];
    const int*   idx = (const int*)d_in[2];
    float* out = (float*)d_out;

    int n = in_sizes[2];

    cudaFuncSetAttribute(seg_sum_kernel,
                         cudaFuncAttributeMaxDynamicSharedMemorySize, SMEM_TOTAL);

    int zb = (out_size / 4 + TPB - 1) / TPB;
    zero_out_kernel<<<zb, TPB>>>(out, out_size);

    int total_stages = n / STAGE_SAMPLES;
    int blocks = 148;
    if (total_stages < blocks) blocks = total_stages > 0 ? total_stages : 1;
    seg_sum_kernel<<<blocks, TPB, SMEM_TOTAL>>>(rgb, w, idx, out, n);
}